// round 15
// baseline (speedup 1.0000x reference)
#include <cuda_runtime.h>
#include <cuda_bf16.h>
#include <cuda_fp16.h>
#include <math.h>

// Problem dims (fixed by reference setup_inputs)
#define BB 4
#define TE 512
#define TD 256
#define DM 256
#define TT 2   // t-rows per CTA in score kernel (2 -> 512 CTAs, high occupancy)

// Scratch (allocation-free __device__ globals). Pads cover prefetch overread.
__device__ __align__(16) __half g_EwH[BB * TE * DM + 2 * DM]; // exp(2*enc@W_a), f16
__device__ __align__(16) float  g_Eu[BB * TD * DM];           // exp(2*dec@U_a), f32

__device__ __forceinline__ float frcp(float x) {
    float y; asm("rcp.approx.ftz.f32 %0, %1;" : "=f"(y) : "f"(x)); return y;
}

// ---------------------------------------------------------------------------
// Combined projection GEMM (enc@W_a and dec@U_a in one launch).
// BM=64, BN=64, BK=16, 256 threads, 4x4/thread, double-buffered.
// Rows 0..2047 -> g_EwH (exp(2x) in HALF), 2048..3071 -> g_Eu (exp(2x) f32).
// ---------------------------------------------------------------------------
__global__ void __launch_bounds__(256)
proj_gemm2(const float* __restrict__ enc, const float* __restrict__ dec,
           const float* __restrict__ Wa,  const float* __restrict__ Ua) {
    __shared__ float sA[2][16][64];   // sA[p][k][m]
    __shared__ float sB[2][16][64];   // sB[p][k][n]

    const int tid = threadIdx.x;
    const int tx = tid & 15;          // n-sub
    const int ty = tid >> 4;          // m-sub
    const int row0 = blockIdx.x * 64;
    const int n0   = blockIdx.y * 64;

    const bool isW = (row0 < BB * TE);
    const float* X;
    const float* W;
    if (isW) { X = enc + (size_t)row0 * DM;              W = Wa; }
    else     { X = dec + (size_t)(row0 - BB * TE) * DM;  W = Ua; }

    float acc[4][4];
#pragma unroll
    for (int i = 0; i < 4; i++)
#pragma unroll
        for (int j = 0; j < 4; j++) acc[i][j] = 0.f;

    const int lm  = tid >> 2;         // 0..63
    const int lkq = tid & 3;          // 0..3
    const int lr  = tid >> 4;         // 0..15
    const int lc  = tid & 15;         // 0..15

    // prologue: tile 0
    float4 av = *(const float4*)(X + lm * DM + 4 * lkq);
    float4 bv = *(const float4*)(W + lr * DM + n0 + 4 * lc);
    sA[0][4 * lkq + 0][lm] = av.x;
    sA[0][4 * lkq + 1][lm] = av.y;
    sA[0][4 * lkq + 2][lm] = av.z;
    sA[0][4 * lkq + 3][lm] = av.w;
    *(float4*)(&sB[0][lr][4 * lc]) = bv;
    __syncthreads();

    int p = 0;
#pragma unroll 1
    for (int kt = 0; kt < 16; kt++) {
        float4 av2, bv2;
        if (kt < 15) {
            av2 = *(const float4*)(X + lm * DM + (kt + 1) * 16 + 4 * lkq);
            bv2 = *(const float4*)(W + ((kt + 1) * 16 + lr) * DM + n0 + 4 * lc);
        }
#pragma unroll
        for (int kk = 0; kk < 16; kk++) {
            float4 a = *(const float4*)(&sA[p][kk][ty * 4]);
            float4 b = *(const float4*)(&sB[p][kk][tx * 4]);
            acc[0][0] += a.x * b.x; acc[0][1] += a.x * b.y; acc[0][2] += a.x * b.z; acc[0][3] += a.x * b.w;
            acc[1][0] += a.y * b.x; acc[1][1] += a.y * b.y; acc[1][2] += a.y * b.z; acc[1][3] += a.y * b.w;
            acc[2][0] += a.z * b.x; acc[2][1] += a.z * b.y; acc[2][2] += a.z * b.z; acc[2][3] += a.z * b.w;
            acc[3][0] += a.w * b.x; acc[3][1] += a.w * b.y; acc[3][2] += a.w * b.z; acc[3][3] += a.w * b.w;
        }
        if (kt < 15) {
            sA[p ^ 1][4 * lkq + 0][lm] = av2.x;
            sA[p ^ 1][4 * lkq + 1][lm] = av2.y;
            sA[p ^ 1][4 * lkq + 2][lm] = av2.z;
            sA[p ^ 1][4 * lkq + 3][lm] = av2.w;
            *(float4*)(&sB[p ^ 1][lr][4 * lc]) = bv2;
        }
        __syncthreads();
        p ^= 1;
    }

    // Epilogue: exp(2*acc). Ew -> half, Eu -> f32.
    if (isW) {
        __half* Y = g_EwH + (size_t)row0 * DM;
#pragma unroll
        for (int i = 0; i < 4; i++) {
            __half2 p0 = __floats2half2_rn(__expf(2.f * acc[i][0]),
                                           __expf(2.f * acc[i][1]));
            __half2 p1 = __floats2half2_rn(__expf(2.f * acc[i][2]),
                                           __expf(2.f * acc[i][3]));
            uint2 o;
            o.x = *reinterpret_cast<unsigned*>(&p0);
            o.y = *reinterpret_cast<unsigned*>(&p1);
            *(uint2*)(Y + (ty * 4 + i) * DM + n0 + tx * 4) = o;
        }
    } else {
        float* Y = g_Eu + (size_t)(row0 - BB * TE) * DM;
#pragma unroll
        for (int i = 0; i < 4; i++) {
            float4 o = make_float4(__expf(2.f * acc[i][0]), __expf(2.f * acc[i][1]),
                                   __expf(2.f * acc[i][2]), __expf(2.f * acc[i][3]));
            *(float4*)(Y + (ty * 4 + i) * DM + n0 + tx * 4) = o;
        }
    }
}

// ---------------------------------------------------------------------------
// FUSED kernel: score (exp-identity + paired rcp) -> softmax -> context.
//   tanh(w+u) = 1 - 2/(Ew*Eu + 1);  sum_d v_d is const per (b,t) -> cancels.
//   score'[t,e] = sum_d v'_d / (Ew[e,d]*Eu[t,d] + 1),  v' = -2v.
//   Pairs share one rcp:  v0/d0 + v1/d1 = (v0*d1 + v1*d0) * rcp(d0*d1).
// Grid: B*(TD/TT) = 512 CTAs x 256 threads -> ~3.5 CTAs/SM (occupancy fix).
// Warp w -> e-block [w*64,(w+1)*64); lane owns 8 d's (ONE LDG.128 of half
// Ew per e-row); TT=2 t's per Ew-load.
// ---------------------------------------------------------------------------
__global__ void __launch_bounds__(256)
attn_score(const float* __restrict__ enc, const float* __restrict__ Va,
           float* __restrict__ out_ctx, float* __restrict__ out_attn) {
    __shared__ __align__(16) float s_eu[TT * DM];          // 2 KB (staging)
    __shared__ __align__(16) float s_v[DM];                // 1 KB (holds -2v)
    __shared__ __align__(16) float s_score[TE][TT];        // 4 KB, e-major

    const int b    = blockIdx.x >> 7;
    const int t0   = (blockIdx.x & 127) * TT;
    const int tid  = threadIdx.x;
    const int warp = tid >> 5;
    const int lane = tid & 31;

    // ---- Phase A: stage Eu rows and v' = -2v ----
    {
        if (tid < TT * DM / 4)
            ((float4*)s_eu)[tid] = ((const float4*)(g_Eu + (size_t)(b * TD + t0) * DM))[tid];
        else if (tid < TT * DM / 4 + 64) {
            const int i = tid - TT * DM / 4;
            float4 v4 = ((const float4*)Va)[i];
            ((float4*)s_v)[i] = make_float4(-2.f * v4.x, -2.f * v4.y,
                                            -2.f * v4.z, -2.f * v4.w);
        }
    }
    __syncthreads();

    // ---- Phase B: scores ----
    {
        const int dl = lane * 8;          // d-base for this lane
        const int eb = warp * 64;         // e-block

        // hoist Eu for both t's (16 regs) and v' (8 regs)
        float eu[TT][8];
#pragma unroll
        for (int t = 0; t < TT; t++) {
            const float4* up = (const float4*)(s_eu + t * DM + dl);
            *(float4*)(&eu[t][0]) = up[0];
            *(float4*)(&eu[t][4]) = up[1];
        }
        float v[8];
        {
            const float4* vp = (const float4*)(s_v + dl);
            *(float4*)(&v[0]) = vp[0];
            *(float4*)(&v[4]) = vp[1];
        }

        const uint4* wr = (const uint4*)(g_EwH + ((size_t)(b * TE) + eb) * DM + dl);
        uint4 cur = *wr;

#pragma unroll 1
        for (int it = 0; it < 64; it++) {
            // prefetch next e-row (pad overread on final iter; values unused)
            wr += DM / 8;
            uint4 nxt = *wr;

            // convert 8 halves -> 8 floats
            float w8[8];
            {
                const __half2* h = (const __half2*)&cur;
#pragma unroll
                for (int q = 0; q < 4; q++) {
                    float2 f = __half22float2(h[q]);
                    w8[2 * q]     = f.x;
                    w8[2 * q + 1] = f.y;
                }
            }

            float s4[TT];
#pragma unroll
            for (int t = 0; t < TT; t++) {
                float a0 = 0.f, a1 = 0.f;
#pragma unroll
                for (int j = 0; j < 8; j += 4) {
                    // pair 0: d j, j+1
                    float d0 = fmaf(w8[j],     eu[t][j],     1.f);
                    float d1 = fmaf(w8[j + 1], eu[t][j + 1], 1.f);
                    float p0 = d0 * d1;
                    float n0 = v[j] * d1;
                    n0 = fmaf(v[j + 1], d0, n0);
                    a0 = fmaf(n0, frcp(p0), a0);
                    // pair 1: d j+2, j+3
                    float d2 = fmaf(w8[j + 2], eu[t][j + 2], 1.f);
                    float d3 = fmaf(w8[j + 3], eu[t][j + 3], 1.f);
                    float p1 = d2 * d3;
                    float n1 = v[j + 2] * d3;
                    n1 = fmaf(v[j + 3], d2, n1);
                    a1 = fmaf(n1, frcp(p1), a1);
                }
                s4[t] = a0 + a1;
            }
            // butterfly over all 32 lanes (d fully reduced)
#pragma unroll
            for (int off = 16; off > 0; off >>= 1) {
                s4[0] += __shfl_xor_sync(0xffffffffu, s4[0], off);
                s4[1] += __shfl_xor_sync(0xffffffffu, s4[1], off);
            }
            if (lane == 0)
                *(float2*)(&s_score[eb + it][0]) = make_float2(s4[0], s4[1]);

            cur = nxt;
        }
    }
    __syncthreads();

    // ---- Phase C: softmax over e (warps 0..1, one t each) ----
    // Writes attn weights to gmem AND back into s_score for fused Phase D.
    if (warp < TT) {
        const int t = warp;
        float vals[16];
        float mx = -1e30f;
#pragma unroll
        for (int k = 0; k < 16; k++) {
            vals[k] = s_score[lane + 32 * k][t];
            mx = fmaxf(mx, vals[k]);
        }
#pragma unroll
        for (int off = 16; off > 0; off >>= 1)
            mx = fmaxf(mx, __shfl_xor_sync(0xffffffffu, mx, off));
        float sum = 0.f;
#pragma unroll
        for (int k = 0; k < 16; k++) {
            vals[k] = exp2f((vals[k] - mx) * 1.4426950408889634f);
            sum += vals[k];
        }
#pragma unroll
        for (int off = 16; off > 0; off >>= 1)
            sum += __shfl_xor_sync(0xffffffffu, sum, off);
        const float inv = 1.0f / sum;
        float* arow = out_attn + ((size_t)(b * TD + t0 + t)) * TE;
#pragma unroll
        for (int k = 0; k < 16; k++) {
            const float w = vals[k] * inv;
            s_score[lane + 32 * k][t] = w;
            arow[lane + 32 * k] = w;
        }
    }
    __syncthreads();

    // ---- Phase D: context = attn @ enc. Thread owns d = tid. ----
    {
        const int d = tid;
        const float* encp = enc + (size_t)b * TE * DM + d;
        float a0 = 0.f, a1 = 0.f;
#pragma unroll 8
        for (int e = 0; e < TE; e++) {
            const float ev = __ldg(encp + (size_t)e * DM);
            float2 aw = *(const float2*)(&s_score[e][0]);
            a0 = fmaf(aw.x, ev, a0);
            a1 = fmaf(aw.y, ev, a1);
        }
        out_ctx[((size_t)(b * TD + t0 + 0)) * DM + d] = a0;
        out_ctx[((size_t)(b * TD + t0 + 1)) * DM + d] = a1;
    }
}

extern "C" void kernel_launch(void* const* d_in, const int* in_sizes, int n_in,
                              void* d_out, int out_size) {
    const float* enc = (const float*)d_in[0];   // [4,512,256]
    const float* dec = (const float*)d_in[1];   // [4,256,256]
    const float* Wa  = (const float*)d_in[2];   // [256,256]
    const float* Ua  = (const float*)d_in[3];   // [256,256]
    const float* Va  = (const float*)d_in[4];   // [256,1]

    float* out      = (float*)d_out;
    float* out_ctx  = out;                          // [4,256,256]
    float* out_attn = out + (size_t)BB * TD * DM;   // [4,256,512]

    // Projections + exp epilogue (Ew half, Eu f32): 192 CTAs
    proj_gemm2<<<dim3((BB * TE + BB * TD) / 64, DM / 64), 256>>>(enc, dec, Wa, Ua);

    // Fused scores + softmax + context: 512 CTAs x 256 threads
    attn_score<<<BB * (TD / TT), 256>>>(enc, Va, out_ctx, out_attn);
}

// round 16
// speedup vs baseline: 1.1507x; 1.1507x over previous
#include <cuda_runtime.h>
#include <cuda_bf16.h>
#include <cuda_fp16.h>
#include <math.h>

// Problem dims (fixed by reference setup_inputs)
#define BB 4
#define TE 512
#define TD 256
#define DM 256
#define TT 4   // t-rows per CTA in score kernel

// Scratch (allocation-free __device__ globals). Pads cover prefetch overread.
__device__ __align__(16) __half g_EwH[BB * TE * DM + 2 * DM]; // exp(2*enc@W_a), f16
__device__ __align__(16) float  g_Eu[BB * TD * DM];           // exp(2*dec@U_a), f32

__device__ __forceinline__ float frcp(float x) {
    float y; asm("rcp.approx.ftz.f32 %0, %1;" : "=f"(y) : "f"(x)); return y;
}

// ---------------------------------------------------------------------------
// Combined projection GEMM (enc@W_a and dec@U_a in one launch).
// BM=64, BN=64, BK=16, 256 threads, 4x4/thread, double-buffered.
// Rows 0..2047 -> g_EwH (exp(2x) in HALF), 2048..3071 -> g_Eu (exp(2x) f32).
// ---------------------------------------------------------------------------
__global__ void __launch_bounds__(256)
proj_gemm2(const float* __restrict__ enc, const float* __restrict__ dec,
           const float* __restrict__ Wa,  const float* __restrict__ Ua) {
    __shared__ float sA[2][16][64];   // sA[p][k][m]
    __shared__ float sB[2][16][64];   // sB[p][k][n]

    const int tid = threadIdx.x;
    const int tx = tid & 15;          // n-sub
    const int ty = tid >> 4;          // m-sub
    const int row0 = blockIdx.x * 64;
    const int n0   = blockIdx.y * 64;

    const bool isW = (row0 < BB * TE);
    const float* X;
    const float* W;
    if (isW) { X = enc + (size_t)row0 * DM;              W = Wa; }
    else     { X = dec + (size_t)(row0 - BB * TE) * DM;  W = Ua; }

    float acc[4][4];
#pragma unroll
    for (int i = 0; i < 4; i++)
#pragma unroll
        for (int j = 0; j < 4; j++) acc[i][j] = 0.f;

    const int lm  = tid >> 2;         // 0..63
    const int lkq = tid & 3;          // 0..3
    const int lr  = tid >> 4;         // 0..15
    const int lc  = tid & 15;         // 0..15

    // prologue: tile 0
    float4 av = *(const float4*)(X + lm * DM + 4 * lkq);
    float4 bv = *(const float4*)(W + lr * DM + n0 + 4 * lc);
    sA[0][4 * lkq + 0][lm] = av.x;
    sA[0][4 * lkq + 1][lm] = av.y;
    sA[0][4 * lkq + 2][lm] = av.z;
    sA[0][4 * lkq + 3][lm] = av.w;
    *(float4*)(&sB[0][lr][4 * lc]) = bv;
    __syncthreads();

    int p = 0;
#pragma unroll 1
    for (int kt = 0; kt < 16; kt++) {
        float4 av2, bv2;
        if (kt < 15) {
            av2 = *(const float4*)(X + lm * DM + (kt + 1) * 16 + 4 * lkq);
            bv2 = *(const float4*)(W + ((kt + 1) * 16 + lr) * DM + n0 + 4 * lc);
        }
#pragma unroll
        for (int kk = 0; kk < 16; kk++) {
            float4 a = *(const float4*)(&sA[p][kk][ty * 4]);
            float4 b = *(const float4*)(&sB[p][kk][tx * 4]);
            acc[0][0] += a.x * b.x; acc[0][1] += a.x * b.y; acc[0][2] += a.x * b.z; acc[0][3] += a.x * b.w;
            acc[1][0] += a.y * b.x; acc[1][1] += a.y * b.y; acc[1][2] += a.y * b.z; acc[1][3] += a.y * b.w;
            acc[2][0] += a.z * b.x; acc[2][1] += a.z * b.y; acc[2][2] += a.z * b.z; acc[2][3] += a.z * b.w;
            acc[3][0] += a.w * b.x; acc[3][1] += a.w * b.y; acc[3][2] += a.w * b.z; acc[3][3] += a.w * b.w;
        }
        if (kt < 15) {
            sA[p ^ 1][4 * lkq + 0][lm] = av2.x;
            sA[p ^ 1][4 * lkq + 1][lm] = av2.y;
            sA[p ^ 1][4 * lkq + 2][lm] = av2.z;
            sA[p ^ 1][4 * lkq + 3][lm] = av2.w;
            *(float4*)(&sB[p ^ 1][lr][4 * lc]) = bv2;
        }
        __syncthreads();
        p ^= 1;
    }

    // Epilogue: exp(2*acc). Ew -> half, Eu -> f32.
    if (isW) {
        __half* Y = g_EwH + (size_t)row0 * DM;
#pragma unroll
        for (int i = 0; i < 4; i++) {
            __half2 p0 = __floats2half2_rn(__expf(2.f * acc[i][0]),
                                           __expf(2.f * acc[i][1]));
            __half2 p1 = __floats2half2_rn(__expf(2.f * acc[i][2]),
                                           __expf(2.f * acc[i][3]));
            uint2 o;
            o.x = *reinterpret_cast<unsigned*>(&p0);
            o.y = *reinterpret_cast<unsigned*>(&p1);
            *(uint2*)(Y + (ty * 4 + i) * DM + n0 + tx * 4) = o;
        }
    } else {
        float* Y = g_Eu + (size_t)(row0 - BB * TE) * DM;
#pragma unroll
        for (int i = 0; i < 4; i++) {
            float4 o = make_float4(__expf(2.f * acc[i][0]), __expf(2.f * acc[i][1]),
                                   __expf(2.f * acc[i][2]), __expf(2.f * acc[i][3]));
            *(float4*)(Y + (ty * 4 + i) * DM + n0 + tx * 4) = o;
        }
    }
}

// ---------------------------------------------------------------------------
// FUSED kernel: score (exp-identity + paired rcp) -> softmax -> context.
//   tanh(w+u) = 1 - 2/(Ew*Eu + 1);  sum_d v_d is const per (b,t) -> cancels.
//   score'[t,e] = sum_d v'_d / (Ew[e,d]*Eu[t,d] + 1),  v' = -2v.
//   Pairs share one rcp:  v0/d0 + v1/d1 = (v0*d1 + v1*d0) * rcp(d0*d1).
// Grid: B*(TD/TT) = 256 CTAs x 512 threads (16 warps; 2 CTAs/SM -> high occ).
// Warp w -> e-block [w*32,(w+1)*32); lane owns 8 d's (ONE LDG.128 of half
// Ew per e-row); 4 t's per Ew-load (amortization kept).
// Phase D: e-range split across thread halves, SMEM reduce.
// ---------------------------------------------------------------------------
__global__ void __launch_bounds__(512)
attn_score(const float* __restrict__ enc, const float* __restrict__ Va,
           float* __restrict__ out_ctx, float* __restrict__ out_attn) {
    __shared__ __align__(16) float s_eu[TT * DM];          // 4 KB (staging)
    __shared__ __align__(16) float s_v[DM];                // 1 KB (holds -2v)
    __shared__ __align__(16) float s_score[TE][TT];        // 8 KB, e-major
    __shared__ __align__(16) float s_red[TT * DM];         // 4 KB (Phase D)

    const int b    = blockIdx.x >> 6;
    const int t0   = (blockIdx.x & 63) * TT;
    const int tid  = threadIdx.x;
    const int warp = tid >> 5;
    const int lane = tid & 31;

    // ---- Phase A: stage Eu rows and v' = -2v ----
    {
        if (tid < 256)
            ((float4*)s_eu)[tid] = ((const float4*)(g_Eu + (size_t)(b * TD + t0) * DM))[tid];
        else if (tid < 320) {
            const int i = tid - 256;
            float4 v4 = ((const float4*)Va)[i];
            ((float4*)s_v)[i] = make_float4(-2.f * v4.x, -2.f * v4.y,
                                            -2.f * v4.z, -2.f * v4.w);
        }
    }
    __syncthreads();

    // ---- Phase B: scores ----
    {
        const int dl = lane * 8;          // d-base for this lane
        const int eb = warp * 32;         // e-block (16 warps x 32 e's)

        // hoist Eu for all 4 t's (32 regs) and v' (8 regs)
        float eu[TT][8];
#pragma unroll
        for (int t = 0; t < TT; t++) {
            const float4* up = (const float4*)(s_eu + t * DM + dl);
            *(float4*)(&eu[t][0]) = up[0];
            *(float4*)(&eu[t][4]) = up[1];
        }
        float v[8];
        {
            const float4* vp = (const float4*)(s_v + dl);
            *(float4*)(&v[0]) = vp[0];
            *(float4*)(&v[4]) = vp[1];
        }

        const uint4* wr = (const uint4*)(g_EwH + ((size_t)(b * TE) + eb) * DM + dl);
        uint4 cur = *wr;

#pragma unroll 1
        for (int it = 0; it < 32; it++) {
            // prefetch next e-row (pad overread on final iter; values unused)
            wr += DM / 8;
            uint4 nxt = *wr;

            // convert 8 halves -> 8 floats
            float w8[8];
            {
                const __half2* h = (const __half2*)&cur;
#pragma unroll
                for (int q = 0; q < 4; q++) {
                    float2 f = __half22float2(h[q]);
                    w8[2 * q]     = f.x;
                    w8[2 * q + 1] = f.y;
                }
            }

            float s4[TT];
#pragma unroll
            for (int t = 0; t < TT; t++) {
                float a0 = 0.f, a1 = 0.f;
#pragma unroll
                for (int j = 0; j < 8; j += 4) {
                    // pair 0: d j, j+1
                    float d0 = fmaf(w8[j],     eu[t][j],     1.f);
                    float d1 = fmaf(w8[j + 1], eu[t][j + 1], 1.f);
                    float p0 = d0 * d1;
                    float n0 = v[j] * d1;
                    n0 = fmaf(v[j + 1], d0, n0);
                    a0 = fmaf(n0, frcp(p0), a0);
                    // pair 1: d j+2, j+3
                    float d2 = fmaf(w8[j + 2], eu[t][j + 2], 1.f);
                    float d3 = fmaf(w8[j + 3], eu[t][j + 3], 1.f);
                    float p1 = d2 * d3;
                    float n1 = v[j + 2] * d3;
                    n1 = fmaf(v[j + 3], d2, n1);
                    a1 = fmaf(n1, frcp(p1), a1);
                }
                s4[t] = a0 + a1;
            }
            // butterfly over all 32 lanes (d fully reduced)
#pragma unroll
            for (int off = 16; off > 0; off >>= 1) {
                s4[0] += __shfl_xor_sync(0xffffffffu, s4[0], off);
                s4[1] += __shfl_xor_sync(0xffffffffu, s4[1], off);
                s4[2] += __shfl_xor_sync(0xffffffffu, s4[2], off);
                s4[3] += __shfl_xor_sync(0xffffffffu, s4[3], off);
            }
            if (lane == 0)
                *(float4*)(&s_score[eb + it][0]) = make_float4(s4[0], s4[1], s4[2], s4[3]);

            cur = nxt;
        }
    }
    __syncthreads();

    // ---- Phase C: softmax over e (warps 0..3, one t each) ----
    // Writes attn weights to gmem AND back into s_score for fused Phase D.
    if (warp < TT) {
        const int t = warp;
        float vals[16];
        float mx = -1e30f;
#pragma unroll
        for (int k = 0; k < 16; k++) {
            vals[k] = s_score[lane + 32 * k][t];
            mx = fmaxf(mx, vals[k]);
        }
#pragma unroll
        for (int off = 16; off > 0; off >>= 1)
            mx = fmaxf(mx, __shfl_xor_sync(0xffffffffu, mx, off));
        float sum = 0.f;
#pragma unroll
        for (int k = 0; k < 16; k++) {
            vals[k] = exp2f((vals[k] - mx) * 1.4426950408889634f);
            sum += vals[k];
        }
#pragma unroll
        for (int off = 16; off > 0; off >>= 1)
            sum += __shfl_xor_sync(0xffffffffu, sum, off);
        const float inv = 1.0f / sum;
        float* arow = out_attn + ((size_t)(b * TD + t0 + t)) * TE;
#pragma unroll
        for (int k = 0; k < 16; k++) {
            const float w = vals[k] * inv;
            s_score[lane + 32 * k][t] = w;
            arow[lane + 32 * k] = w;
        }
    }
    __syncthreads();

    // ---- Phase D: context = attn @ enc (e-range split across halves) ----
    {
        const int d = tid & 255;
        const int h = tid >> 8;           // 0 or 1: e-half
        const float* encp = enc + (size_t)b * TE * DM + (size_t)h * 256 * DM + d;
        float a0 = 0.f, a1 = 0.f, a2 = 0.f, a3 = 0.f;
#pragma unroll 8
        for (int e = 0; e < 256; e++) {
            const float ev = __ldg(encp + (size_t)e * DM);
            float4 aw = *(const float4*)(&s_score[h * 256 + e][0]);
            a0 = fmaf(aw.x, ev, a0);
            a1 = fmaf(aw.y, ev, a1);
            a2 = fmaf(aw.z, ev, a2);
            a3 = fmaf(aw.w, ev, a3);
        }
        if (h == 1) {
            s_red[0 * 256 + d] = a0;
            s_red[1 * 256 + d] = a1;
            s_red[2 * 256 + d] = a2;
            s_red[3 * 256 + d] = a3;
        }
        __syncthreads();
        if (h == 0) {
            a0 += s_red[0 * 256 + d];
            a1 += s_red[1 * 256 + d];
            a2 += s_red[2 * 256 + d];
            a3 += s_red[3 * 256 + d];
            out_ctx[((size_t)(b * TD + t0 + 0)) * DM + d] = a0;
            out_ctx[((size_t)(b * TD + t0 + 1)) * DM + d] = a1;
            out_ctx[((size_t)(b * TD + t0 + 2)) * DM + d] = a2;
            out_ctx[((size_t)(b * TD + t0 + 3)) * DM + d] = a3;
        }
    }
}

extern "C" void kernel_launch(void* const* d_in, const int* in_sizes, int n_in,
                              void* d_out, int out_size) {
    const float* enc = (const float*)d_in[0];   // [4,512,256]
    const float* dec = (const float*)d_in[1];   // [4,256,256]
    const float* Wa  = (const float*)d_in[2];   // [256,256]
    const float* Ua  = (const float*)d_in[3];   // [256,256]
    const float* Va  = (const float*)d_in[4];   // [256,1]

    float* out      = (float*)d_out;
    float* out_ctx  = out;                          // [4,256,256]
    float* out_attn = out + (size_t)BB * TD * DM;   // [4,256,512]

    // Projections + exp epilogue (Ew half, Eu f32): 192 CTAs
    proj_gemm2<<<dim3((BB * TE + BB * TD) / 64, DM / 64), 256>>>(enc, dec, Wa, Ua);

    // Fused scores + softmax + context: 256 CTAs x 512 threads
    attn_score<<<BB * (TD / TT), 512>>>(enc, Va, out_ctx, out_attn);
}